// round 6
// baseline (speedup 1.0000x reference)
#include <cuda_runtime.h>
#include <cuda_bf16.h>
#include <math.h>
#include <stdint.h>

// Problem constants
#define Bc 4
#define Nn 8192
#define Mm 8192
#define Cc 512
#define Hh 8
#define Dd 64
#define SCALEF 0.125f          // D^-0.5
#define NCHUNK 32

// ---------------- scratch (device globals: allocation-free) ----------------
__device__ float g_kfeat[(size_t)Bc * Nn * Cc];
__device__ float g_v[(size_t)Bc * Nn * Cc];
__device__ float g_qfeat[(size_t)Bc * Mm * Cc];
__device__ float g_xatt[(size_t)Bc * Mm * Cc];
__device__ float g_ctx_part[(size_t)Bc * Hh * NCHUNK * Dd * Dd];
__device__ float g_ksum_part[(size_t)Bc * Hh * NCHUNK * Dd];
__device__ float g_ctx[(size_t)Bc * Hh * Dd * Dd];
__device__ float g_ksum[(size_t)Bc * Hh * Dd];
// pre-split weights: rows [0,512)=q_w, [512,1536)=kv_w, [1536,2048)=proj_w
__device__ __nv_bfloat16 g_whi[(size_t)2048 * Cc];
__device__ __nv_bfloat16 g_wlo[(size_t)2048 * Cc];

__device__ __forceinline__ float elu1(float x) {
    return x > 0.0f ? x + 1.0f : expf(x);
}

__device__ __forceinline__ uint32_t smem_to_u32(const void* p) {
    uint32_t a;
    asm("{ .reg .u64 t; cvta.to.shared.u64 t, %1; cvt.u32.u64 %0, t; }"
        : "=r"(a) : "l"(p));
    return a;
}

// ldmatrix / mma / cp.async helpers (baseline PTX — plain sm_103 target)
__device__ __forceinline__ void ldsm_x4(uint32_t* r, uint32_t addr) {
    asm volatile("ldmatrix.sync.aligned.m8n8.x4.shared.b16 {%0,%1,%2,%3}, [%4];"
                 : "=r"(r[0]), "=r"(r[1]), "=r"(r[2]), "=r"(r[3]) : "r"(addr));
}
__device__ __forceinline__ void ldsm_x2(uint32_t* r, uint32_t addr) {
    asm volatile("ldmatrix.sync.aligned.m8n8.x2.shared.b16 {%0,%1}, [%2];"
                 : "=r"(r[0]), "=r"(r[1]) : "r"(addr));
}
__device__ __forceinline__ void mma_bf16(float* c, const uint32_t* a, const uint32_t* b) {
    asm volatile(
        "mma.sync.aligned.m16n8k16.row.col.f32.bf16.bf16.f32 "
        "{%0,%1,%2,%3}, {%4,%5,%6,%7}, {%8,%9}, {%0,%1,%2,%3};"
        : "+f"(c[0]), "+f"(c[1]), "+f"(c[2]), "+f"(c[3])
        : "r"(a[0]), "r"(a[1]), "r"(a[2]), "r"(a[3]), "r"(b[0]), "r"(b[1]));
}
__device__ __forceinline__ void cp_async16(uint32_t dst, const void* src) {
    asm volatile("cp.async.cg.shared.global [%0], [%1], 16;"
                 :: "r"(dst), "l"(src) : "memory");
}
#define CP_COMMIT() asm volatile("cp.async.commit_group;" ::: "memory")
#define CP_WAIT0()  asm volatile("cp.async.wait_group 0;" ::: "memory")

// ---------------- SMEM layout for GEMM (bytes) ------------------------------
// A fp32 stage: 2 x [128][64] f32 = 2 x 32768
// A bf16 tiles (hi+lo), single stage: 2 x 18432  (pitch 144 B, BK=64 + 8 pad)
// B bf16 tiles (hi+lo), double stage: 2 x 2 x 18432
#define TPITCH     144
#define TILE_SZ    18432
#define OFF_STAGE  0
#define STAGE_SZ   32768
#define OFF_A_HI   65536
#define OFF_A_LO   (65536 + TILE_SZ)
#define OFF_BT     (65536 + 2 * TILE_SZ)          // + s*2*TILE_SZ, lo at +TILE_SZ
#define GEMM_SMEM  (OFF_BT + 4 * TILE_SZ)         // 176128

// split fp32 -> (hi,lo) bf16, store 4 cols into padded A tiles
__device__ __forceinline__ void split_store_a(char* smem, int row, int c4, float4 v) {
    float xs[4] = {v.x, v.y, v.z, v.w};
    __nv_bfloat16 hi[4], lo[4];
#pragma unroll
    for (int j = 0; j < 4; j++) {
        hi[j] = __float2bfloat16(xs[j]);
        lo[j] = __float2bfloat16(xs[j] - __bfloat162float(hi[j]));
    }
    uint32_t bo = (uint32_t)row * TPITCH + (uint32_t)c4 * 8;
    *(__nv_bfloat162*)(smem + OFF_A_HI + bo)     = __halves2bfloat162(hi[0], hi[1]);
    *(__nv_bfloat162*)(smem + OFF_A_HI + bo + 4) = __halves2bfloat162(hi[2], hi[3]);
    *(__nv_bfloat162*)(smem + OFF_A_LO + bo)     = __halves2bfloat162(lo[0], lo[1]);
    *(__nv_bfloat162*)(smem + OFF_A_LO + bo + 4) = __halves2bfloat162(lo[2], lo[3]);
}

// ---------------------------------------------------------------------------
// Weight pre-split: fp32 [2048 x 512] (q_w | kv_w | proj_w) -> bf16 hi/lo
// ---------------------------------------------------------------------------
__global__ __launch_bounds__(256) void split_weights_kernel(
    const float* __restrict__ q_w, const float* __restrict__ kv_w,
    const float* __restrict__ proj_w)
{
    int idx = blockIdx.x * 256 + threadIdx.x;   // float4 index, 2048*512/4 total
    int row = idx >> 7;                          // 128 float4 per row
    int c4  = idx & 127;
    const float* src;
    int lrow;
    if (row < 512)       { src = q_w;    lrow = row; }
    else if (row < 1536) { src = kv_w;   lrow = row - 512; }
    else                 { src = proj_w; lrow = row - 1536; }
    float4 v = *(const float4*)(src + (size_t)lrow * Cc + c4 * 4);
    float xs[4] = {v.x, v.y, v.z, v.w};
    __nv_bfloat16 hi[4], lo[4];
#pragma unroll
    for (int j = 0; j < 4; j++) {
        hi[j] = __float2bfloat16(xs[j]);
        lo[j] = __float2bfloat16(xs[j] - __bfloat162float(hi[j]));
    }
    size_t o = (size_t)row * Cc + c4 * 4;
    *(__nv_bfloat162*)(g_whi + o)     = __halves2bfloat162(hi[0], hi[1]);
    *(__nv_bfloat162*)(g_whi + o + 2) = __halves2bfloat162(hi[2], hi[3]);
    *(__nv_bfloat162*)(g_wlo + o)     = __halves2bfloat162(lo[0], lo[1]);
    *(__nv_bfloat162*)(g_wlo + o + 2) = __halves2bfloat162(lo[2], lo[3]);
}

// ---------------------------------------------------------------------------
// HMMA NT GEMM with cp.async 2-stage pipeline.
// out[i,j] = sum_k A[i,k]*W[woff+j,k], K=512, tile 128x128, BK=64.
// bf16 2-term split: hi*hi + hi*lo + lo*hi, fp32 accum.
// MODE 0: col<512 -> elu1 -> g_kfeat ; col>=512 -> g_v   (woff=512, kv_w)
// MODE 1: elu1 -> g_qfeat                                 (woff=0, q_w)
// MODE 2: A = g_xatt, + bias -> outp                      (woff=1536, proj_w)
// ---------------------------------------------------------------------------
template <int MODE>
__global__ __launch_bounds__(256) void gemm_mma(
    const float* __restrict__ A, int woff,
    const float* __restrict__ bias, float* __restrict__ outp)
{
    extern __shared__ char smem[];
    const uint32_t sb = smem_to_u32(smem);
    const int tid  = threadIdx.x;
    const int wid  = tid >> 5;
    const int lane = tid & 31;
    const int warp_m = wid & 3;     // 0..3  (32 rows each)
    const int warp_n = wid >> 2;    // 0..1  (64 cols each)

    const float* Aptr = (MODE == 2) ? g_xatt : A;
    const int m0 = blockIdx.y * 128;
    const int n0 = blockIdx.x * 128;

    // ldmatrix lane address components
    const int aq = lane >> 3, ar = lane & 7;
    const int a_row_base = warp_m * 32 + (aq & 1) * 8 + ar;   // + mt*16
    const int a_colb     = ((aq >> 1) * 8) * 2;               // bytes, + k16*32
    const int br  = lane & 7;
    const int bhf = (lane >> 3) & 1;
    const int b_row_base = warp_n * 64 + br;                  // + nt*8
    const int b_colb     = (bhf * 8) * 2;                     // bytes, + k16*32

    float acc[2][8][4];
#pragma unroll
    for (int mt = 0; mt < 2; mt++)
#pragma unroll
        for (int nt = 0; nt < 8; nt++)
#pragma unroll
            for (int e = 0; e < 4; e++) acc[mt][nt][e] = 0.0f;

    // ---- copy issue helper (A fp32 -> stage[s], B hi/lo -> Btiles[s]) ----
    auto issue_copies = [&](int chunk, int s) {
        const int k0 = chunk * 64;
        // A: 128 rows x 256 B = 2048 granules of 16 B
#pragma unroll
        for (int it = 0; it < 8; it++) {
            int idx = tid + it * 256;
            int row = idx >> 4, g = idx & 15;
            cp_async16(sb + OFF_STAGE + s * STAGE_SZ + row * 256 + g * 16,
                       Aptr + (size_t)(m0 + row) * Cc + k0 + g * 4);
        }
        // B: hi and lo tiles, 128 rows x 128 B each
#pragma unroll
        for (int it = 0; it < 8; it++) {
            int idx = tid + it * 256;          // 0..2047
            int half = idx >> 10;              // 0 hi, 1 lo
            int rem  = idx & 1023;
            int row  = rem >> 3, g = rem & 7;
            const __nv_bfloat16* src =
                (half ? g_wlo : g_whi) + (size_t)(woff + n0 + row) * Cc + k0 + g * 8;
            cp_async16(sb + OFF_BT + s * (2 * TILE_SZ) + half * TILE_SZ
                           + row * TPITCH + g * 16, src);
        }
        CP_COMMIT();
    };

    issue_copies(0, 0);

    for (int chunk = 0; chunk < 8; chunk++) {
        const int s = chunk & 1;
        CP_WAIT0();
        __syncthreads();                 // data visible; all prior MMA done
        if (chunk + 1 < 8) issue_copies(chunk + 1, s ^ 1);

        // convert A fp32 stage[s] -> A hi/lo tiles
        const char* stage = smem + OFF_STAGE + s * STAGE_SZ;
#pragma unroll
        for (int it = 0; it < 8; it++) {
            int idx = tid + it * 256;
            int row = idx >> 4, c4 = idx & 15;
            float4 v = *(const float4*)(stage + row * 256 + c4 * 16);
            split_store_a(smem, row, c4, v);
        }
        __syncthreads();

        const uint32_t bhi_base = sb + OFF_BT + s * (2 * TILE_SZ);
        const uint32_t blo_base = bhi_base + TILE_SZ;
#pragma unroll
        for (int k16 = 0; k16 < 4; k16++) {
            const uint32_t koff = (uint32_t)k16 * 32;
            uint32_t bh[8][2], bl[8][2];
#pragma unroll
            for (int nt = 0; nt < 8; nt++) {
                uint32_t boff = (uint32_t)(b_row_base + nt * 8) * TPITCH + b_colb + koff;
                ldsm_x2(bh[nt], bhi_base + boff);
                ldsm_x2(bl[nt], blo_base + boff);
            }
#pragma unroll
            for (int mt = 0; mt < 2; mt++) {
                uint32_t aoff = (uint32_t)(a_row_base + mt * 16) * TPITCH + a_colb + koff;
                uint32_t ah[4], al[4];
                ldsm_x4(ah, sb + OFF_A_HI + aoff);
                ldsm_x4(al, sb + OFF_A_LO + aoff);
#pragma unroll
                for (int nt = 0; nt < 8; nt++) {
                    mma_bf16(acc[mt][nt], ah, bh[nt]);
                    mma_bf16(acc[mt][nt], ah, bl[nt]);
                    mma_bf16(acc[mt][nt], al, bh[nt]);
                }
            }
        }
    }

    // ---- epilogue: fragment registers -> gmem ----
    const int tr = lane >> 2;
    const int tc = (lane & 3) * 2;
    const bool khalf = (MODE == 0) && (n0 < Cc);

#pragma unroll
    for (int mt = 0; mt < 2; mt++) {
#pragma unroll
        for (int nt = 0; nt < 8; nt++) {
#pragma unroll
            for (int half = 0; half < 2; half++) {
                size_t row = (size_t)(m0 + warp_m * 32 + mt * 16 + tr + half * 8);
                int col = n0 + warp_n * 64 + nt * 8 + tc;
                float v0 = acc[mt][nt][half * 2 + 0];
                float v1 = acc[mt][nt][half * 2 + 1];
                if (MODE == 0) {
                    if (khalf) {
                        *(float2*)(g_kfeat + row * Cc + col) =
                            make_float2(elu1(v0), elu1(v1));
                    } else {
                        *(float2*)(g_v + row * Cc + (col - Cc)) = make_float2(v0, v1);
                    }
                } else if (MODE == 1) {
                    *(float2*)(g_qfeat + row * Cc + col) =
                        make_float2(elu1(v0), elu1(v1));
                } else {
                    *(float2*)(outp + row * Cc + col) =
                        make_float2(v0 + __ldg(bias + col), v1 + __ldg(bias + col + 1));
                }
            }
        }
    }
}

// ---------------------------------------------------------------------------
// ctx partial: per (b,h,chunk) 64x64 K^T V over 256 N-rows + ksum partial.
// ---------------------------------------------------------------------------
__global__ __launch_bounds__(256) void ctx_partial_kernel()
{
    int chunk = blockIdx.x;
    int bh    = blockIdx.y;
    int b = bh / Hh, h = bh % Hh;
    int n0 = chunk * (Nn / NCHUNK);

    __shared__ float Ks[16][64];
    __shared__ float Vs[16][64];

    int tid = threadIdx.x;
    int dg = tid >> 4;
    int eg = tid & 15;

    float acc[4][4];
#pragma unroll
    for (int i = 0; i < 4; i++)
#pragma unroll
        for (int j = 0; j < 4; j++) acc[i][j] = 0.0f;
    float ks[4] = {0.0f, 0.0f, 0.0f, 0.0f};

    const float* Kbase = g_kfeat + (size_t)b * Nn * Cc + h * Dd;
    const float* Vbase = g_v     + (size_t)b * Nn * Cc + h * Dd;

    int lrow = tid >> 4;
    int lc4  = tid & 15;

    for (int r0 = 0; r0 < Nn / NCHUNK; r0 += 16) {
        size_t gro = (size_t)(n0 + r0 + lrow) * Cc + lc4 * 4;
        *(float4*)&Ks[lrow][lc4 * 4] = *(const float4*)(Kbase + gro);
        *(float4*)&Vs[lrow][lc4 * 4] = *(const float4*)(Vbase + gro);
        __syncthreads();
#pragma unroll
        for (int r = 0; r < 16; r++) {
            float4 kv = *(const float4*)&Ks[r][dg * 4];
            float4 vv = *(const float4*)&Vs[r][eg * 4];
            float kr[4] = {kv.x, kv.y, kv.z, kv.w};
            float vr[4] = {vv.x, vv.y, vv.z, vv.w};
#pragma unroll
            for (int i = 0; i < 4; i++)
#pragma unroll
                for (int j = 0; j < 4; j++)
                    acc[i][j] = fmaf(kr[i], vr[j], acc[i][j]);
            if (eg == 0) {
#pragma unroll
                for (int i = 0; i < 4; i++) ks[i] += kr[i];
            }
        }
        __syncthreads();
    }

    float* cp = g_ctx_part + ((size_t)bh * NCHUNK + chunk) * Dd * Dd;
#pragma unroll
    for (int i = 0; i < 4; i++)
#pragma unroll
        for (int j = 0; j < 4; j++)
            cp[(dg * 4 + i) * Dd + eg * 4 + j] = acc[i][j];
    if (eg == 0) {
        float* kp = g_ksum_part + ((size_t)bh * NCHUNK + chunk) * Dd;
#pragma unroll
        for (int i = 0; i < 4; i++) kp[dg * 4 + i] = ks[i];
    }
}

__global__ __launch_bounds__(256) void ctx_reduce_kernel()
{
    int bh = blockIdx.x;
    int tid = threadIdx.x;
    for (int i = tid; i < Dd * Dd; i += 256) {
        float s = 0.0f;
#pragma unroll 4
        for (int c = 0; c < NCHUNK; c++)
            s += g_ctx_part[((size_t)bh * NCHUNK + c) * Dd * Dd + i];
        g_ctx[(size_t)bh * Dd * Dd + i] = s;
    }
    if (tid < Dd) {
        float s = 0.0f;
#pragma unroll 4
        for (int c = 0; c < NCHUNK; c++)
            s += g_ksum_part[((size_t)bh * NCHUNK + c) * Dd + tid];
        g_ksum[(size_t)bh * Dd + tid] = s;
    }
}

// ---------------------------------------------------------------------------
// x = (qfeat @ ctx) * SCALE / (1e-6 + qfeat . ksum)
// ---------------------------------------------------------------------------
__global__ __launch_bounds__(256) void attn_apply_kernel()
{
    int bh = blockIdx.y;
    int b = bh / Hh, h = bh % Hh;
    int m0 = blockIdx.x * 64;

    __shared__ float Cs[64][64];
    __shared__ float Qs[64][64];
    __shared__ float ksum_s[64];
    __shared__ float pden[64][4];
    __shared__ float den[64];

    int tid = threadIdx.x;

    {
        const float4* src = (const float4*)(g_ctx + (size_t)bh * Dd * Dd);
        float4* dst = (float4*)&Cs[0][0];
        for (int i = tid; i < 1024; i += 256) dst[i] = src[i];
    }
    if (tid < 64) ksum_s[tid] = g_ksum[(size_t)bh * Dd + tid];

    for (int i = tid; i < 1024; i += 256) {
        int row = i >> 4;
        int c4  = i & 15;
        *(float4*)&Qs[row][c4 * 4] =
            *(const float4*)(g_qfeat + ((size_t)b * Mm + m0 + row) * Cc + h * Dd + c4 * 4);
    }
    __syncthreads();

    {
        int row = tid >> 2;
        int qq  = tid & 3;
        float s = 0.0f;
#pragma unroll
        for (int d4 = 0; d4 < 4; d4++) {
            float4 qv = *(const float4*)&Qs[row][qq * 16 + d4 * 4];
            float4 kv = *(const float4*)&ksum_s[qq * 16 + d4 * 4];
            s += qv.x * kv.x + qv.y * kv.y + qv.z * kv.z + qv.w * kv.w;
        }
        pden[row][qq] = s;
    }
    __syncthreads();
    if (tid < 64) {
        float d0 = pden[tid][0] + pden[tid][1] + pden[tid][2] + pden[tid][3];
        den[tid] = SCALEF / (1e-6f + d0);
    }
    __syncthreads();

    int rg = tid >> 4;
    int eg = tid & 15;

    float acc[4][4];
#pragma unroll
    for (int i = 0; i < 4; i++)
#pragma unroll
        for (int j = 0; j < 4; j++) acc[i][j] = 0.0f;

#pragma unroll 4
    for (int d = 0; d < 64; d++) {
        float4 cv = *(const float4*)&Cs[d][eg * 4];
        float q0 = Qs[rg * 4 + 0][d];
        float q1 = Qs[rg * 4 + 1][d];
        float q2 = Qs[rg * 4 + 2][d];
        float q3 = Qs[rg * 4 + 3][d];
        acc[0][0] = fmaf(q0, cv.x, acc[0][0]); acc[0][1] = fmaf(q0, cv.y, acc[0][1]);
        acc[0][2] = fmaf(q0, cv.z, acc[0][2]); acc[0][3] = fmaf(q0, cv.w, acc[0][3]);
        acc[1][0] = fmaf(q1, cv.x, acc[1][0]); acc[1][1] = fmaf(q1, cv.y, acc[1][1]);
        acc[1][2] = fmaf(q1, cv.z, acc[1][2]); acc[1][3] = fmaf(q1, cv.w, acc[1][3]);
        acc[2][0] = fmaf(q2, cv.x, acc[2][0]); acc[2][1] = fmaf(q2, cv.y, acc[2][1]);
        acc[2][2] = fmaf(q2, cv.z, acc[2][2]); acc[2][3] = fmaf(q2, cv.w, acc[2][3]);
        acc[3][0] = fmaf(q3, cv.x, acc[3][0]); acc[3][1] = fmaf(q3, cv.y, acc[3][1]);
        acc[3][2] = fmaf(q3, cv.z, acc[3][2]); acc[3][3] = fmaf(q3, cv.w, acc[3][3]);
    }

#pragma unroll
    for (int i = 0; i < 4; i++) {
        float dv = den[rg * 4 + i];
        float4 o;
        o.x = acc[i][0] * dv;
        o.y = acc[i][1] * dv;
        o.z = acc[i][2] * dv;
        o.w = acc[i][3] * dv;
        *(float4*)(g_xatt + ((size_t)b * Mm + m0 + rg * 4 + i) * Cc + h * Dd + eg * 4) = o;
    }
}

// ---------------------------------------------------------------------------
extern "C" void kernel_launch(void* const* d_in, const int* in_sizes, int n_in,
                              void* d_out, int out_size)
{
    const float* target = (const float*)d_in[0];
    const float* refer  = (const float*)d_in[1];
    const float* q_w    = (const float*)d_in[2];
    const float* kv_w   = (const float*)d_in[3];
    const float* proj_w = (const float*)d_in[4];
    const float* proj_b = (const float*)d_in[5];
    float* out = (float*)d_out;

    cudaFuncSetAttribute(gemm_mma<0>, cudaFuncAttributeMaxDynamicSharedMemorySize, GEMM_SMEM);
    cudaFuncSetAttribute(gemm_mma<1>, cudaFuncAttributeMaxDynamicSharedMemorySize, GEMM_SMEM);
    cudaFuncSetAttribute(gemm_mma<2>, cudaFuncAttributeMaxDynamicSharedMemorySize, GEMM_SMEM);

    // 0) pre-split weights to bf16 hi/lo
    split_weights_kernel<<<1024, 256>>>(q_w, kv_w, proj_w);
    // 1) kv projection + elu on K half
    gemm_mma<0><<<dim3((2 * Cc) / 128, (Bc * Nn) / 128), 256, GEMM_SMEM>>>(refer, 512, nullptr, nullptr);
    // 2) ctx + ksum
    ctx_partial_kernel<<<dim3(NCHUNK, Bc * Hh), 256>>>();
    ctx_reduce_kernel<<<Bc * Hh, 256>>>();
    // 3) q projection + elu
    gemm_mma<1><<<dim3(Cc / 128, (Bc * Mm) / 128), 256, GEMM_SMEM>>>(target, 0, nullptr, nullptr);
    // 4) attention apply
    attn_apply_kernel<<<dim3(Mm / 64, Bc * Hh), 256>>>();
    // 5) output projection + bias
    gemm_mma<2><<<dim3(Cc / 128, (Bc * Mm) / 128), 256, GEMM_SMEM>>>(nullptr, 1536, proj_b, out);
}